// round 14
// baseline (speedup 1.0000x reference)
#include <cuda_runtime.h>
#include <cstdint>

#define B_   8
#define C_   64
#define NPTS 2048
#define MFRQ 4032
#define F1   2048

// -------- scratch (device globals; no allocation in kernel_launch) ----------
__device__ __align__(16) float2 g_Xft[B_ * C_ * F1];    // forward result {re, im}, [b][c][f]
__device__ __align__(16) float  g_xfre[B_ * C_ * MFRQ]; // xf re plane (tf32-rounded)
__device__ __align__(16) float  g_xfmi[B_ * C_ * MFRQ]; // xf minus-im plane (tf32-rounded)
__device__ __align__(16) float  g_pvre[(size_t)NPTS * MFRQ]; // rna-rounded Vi_re
__device__ __align__(16) float  g_pvim[(size_t)NPTS * MFRQ]; // rna-rounded Vi_im
__device__ float2 g_phi[2 * B_ * 1024];                 // [mod][b][x(32)][y(32)]

// -------- packed f32x2 helpers (k_mix) --------------------------------------
__device__ __forceinline__ unsigned long long pack2(float lo, float hi) {
    unsigned long long r;
    asm("mov.b64 %0, {%1, %2};" : "=l"(r) : "f"(lo), "f"(hi));
    return r;
}
__device__ __forceinline__ float2 unpack2(unsigned long long v) {
    float2 r;
    asm("mov.b64 {%0, %1}, %2;" : "=f"(r.x), "=f"(r.y) : "l"(v));
    return r;
}
__device__ __forceinline__ void fma2(unsigned long long &d,
                                     unsigned long long a,
                                     unsigned long long b) {
    asm("fma.rn.f32x2 %0, %1, %2, %0;" : "+l"(d) : "l"(a), "l"(b));
}

// -------- tf32 mma.sync / cp.async helpers (portable PTX, compute_80+) ------
#define SWZ(o) ((o) ^ (((o) >> 3) & 0x70))

__device__ __forceinline__ uint32_t f2tf(float f) {
    uint32_t r;
    asm("cvt.rna.tf32.f32 %0, %1;" : "=r"(r) : "f"(f));
    return r;
}
__device__ __forceinline__ float f2tf_f(float f) {
    return __uint_as_float(f2tf(f));
}
__device__ __forceinline__ uint4 cvt4(float4 v) {
    uint4 r;
    r.x = f2tf(v.x); r.y = f2tf(v.y); r.z = f2tf(v.z); r.w = f2tf(v.w);
    return r;
}
__device__ __forceinline__ void mma8(float* d, const uint32_t* a,
                                     uint32_t b0, uint32_t b1) {
    asm volatile(
        "mma.sync.aligned.m16n8k8.row.col.f32.tf32.tf32.f32 "
        "{%0,%1,%2,%3}, {%4,%5,%6,%7}, {%8,%9}, {%0,%1,%2,%3};"
        : "+f"(d[0]), "+f"(d[1]), "+f"(d[2]), "+f"(d[3])
        : "r"(a[0]), "r"(a[1]), "r"(a[2]), "r"(a[3]), "r"(b0), "r"(b1));
}
__device__ __forceinline__ uint32_t smem_u32(const void* p) {
    uint32_t a;
    asm("{ .reg .u64 t; cvta.to.shared.u64 t, %1; cvt.u32.u64 %0, t; }"
        : "=r"(a) : "l"(p));
    return a;
}
__device__ __forceinline__ void cpa16(uint32_t dst, const void* src) {
    asm volatile("cp.async.ca.shared.global [%0], [%1], 16;"
                 :: "r"(dst), "l"(src) : "memory");
}
#define CP_COMMIT() asm volatile("cp.async.commit_group;" ::: "memory")
#define CP_WAIT1()  asm volatile("cp.async.wait_group 1;" ::: "memory")
#define CP_WAIT0()  asm volatile("cp.async.wait_group 0;" ::: "memory")

// ============================================================================
// Kernel 0a: zero the output (split-K inverse accumulates atomically)
// ============================================================================
__global__ __launch_bounds__(256) void k_zero(float* __restrict__ out)
{
    const size_t i = ((size_t)blockIdx.x * 256 + threadIdx.x) * 4;
    *reinterpret_cast<float4*>(out + i) = make_float4(0.f, 0.f, 0.f, 0.f);
}

// ============================================================================
// Kernel 0b: pre-round Vi planes to tf32 (rna) once per launch.
// grid (8064, 2): y=0 -> re, y=1 -> im.  8,257,536 floats per plane.
// ============================================================================
__global__ __launch_bounds__(256) void k_preround(
    const float* __restrict__ vire, const float* __restrict__ viim)
{
    const float* src = blockIdx.y ? viim : vire;
    float* dst = blockIdx.y ? g_pvim : g_pvre;
    const size_t i = ((size_t)blockIdx.x * 256 + threadIdx.x) * 4;
    float4 v = *reinterpret_cast<const float4*>(src + i);
    v.x = f2tf_f(v.x); v.y = f2tf_f(v.y); v.z = f2tf_f(v.z); v.w = f2tf_f(v.w);
    *reinterpret_cast<float4*>(dst + i) = v;
}

// ============================================================================
// Kernel 1: phi[b,x,y] = sum_e mod[x,y,e] * emb[b,e]
// ============================================================================
__global__ __launch_bounds__(256) void k_phi(
    const float* __restrict__ emb,
    const float* __restrict__ m1re, const float* __restrict__ m1im,
    const float* __restrict__ m2re, const float* __restrict__ m2im)
{
    __shared__ float s_re[256];
    __shared__ float s_im[256];
    const int bid = blockIdx.x;
    const int mod = bid >> 10;
    const int xy  = bid & 1023;
    const int tid = threadIdx.x;

    const float* mre = (mod ? m2re : m1re) + (size_t)xy * 256;
    const float* mim = (mod ? m2im : m1im) + (size_t)xy * 256;
    s_re[tid] = mre[tid];
    s_im[tid] = mim[tid];
    __syncthreads();

    const int w = tid >> 5;
    const int l = tid & 31;
    float pr = 0.f, pi = 0.f;
#pragma unroll
    for (int j = 0; j < 8; j++) {
        int e = l + j * 32;
        float ee = emb[w * 256 + e];
        pr += s_re[e] * ee;
        pi += s_im[e] * ee;
    }
#pragma unroll
    for (int off = 16; off > 0; off >>= 1) {
        pr += __shfl_down_sync(0xffffffffu, pr, off);
        pi += __shfl_down_sync(0xffffffffu, pi, off);
    }
    if (l == 0) g_phi[mod * (B_ * 1024) + w * 1024 + xy] = make_float2(pr, pi);
}

// ============================================================================
// Forward NUFT via mma.sync tf32: D[f:128, c:64] = Vf_{re|im} @ x[b]^T.
// grid (16 ftiles, 2 reim, 8 b), 256 threads (8 warps), warp tile 32x32.
// (unchanged from R13)
// ============================================================================
__global__ __launch_bounds__(256, 2) void k_forward(
    const float* __restrict__ x,
    const float* __restrict__ vfre,
    const float* __restrict__ vfim)
{
    __shared__ __align__(128) char sA[2][16384];
    __shared__ __align__(128) char sB[2][8192];

    const int tid  = threadIdx.x;
    const int wid  = tid >> 5;
    const int lane = tid & 31;
    const int g    = lane >> 2;
    const int tig  = lane & 3;
    const int mg   = wid >> 1;
    const int ng   = wid & 1;
    const int ftile = blockIdx.x;
    const int reim  = blockIdx.y;
    const int b     = blockIdx.z;
    const float* vf = reim ? vfim : vfre;
    const float* xb = x + (size_t)b * C_ * NPTS;

    const int arow  = tid >> 1;
    const int ahalf = tid & 1;
    const int fg    = ftile * 128 + arow;
    const int vrow  = (fg >> 5) * 63 + (fg & 31);
    const float* asrc = vf + (size_t)vrow * NPTS + ahalf * 16;
    const int brow = tid >> 2;
    const int bq   = tid & 3;
    const float* bsrc = xb + (size_t)brow * NPTS + bq * 8;

    float d[2][4][4];
#pragma unroll
    for (int i = 0; i < 2; i++)
#pragma unroll
        for (int j = 0; j < 4; j++)
#pragma unroll
            for (int k = 0; k < 4; k++) d[i][j][k] = 0.f;

    float4 pa[4], pb[2];
#pragma unroll
    for (int j = 0; j < 4; j++) pa[j] = *(const float4*)(asrc + 4 * j);
#pragma unroll
    for (int j = 0; j < 2; j++) pb[j] = *(const float4*)(bsrc + 4 * j);
    {
        char* Ad = sA[0]; char* Bd = sB[0];
#pragma unroll
        for (int j = 0; j < 4; j++)
            *(uint4*)(Ad + SWZ(arow * 128 + ahalf * 64 + j * 16)) = cvt4(pa[j]);
#pragma unroll
        for (int j = 0; j < 2; j++)
            *(uint4*)(Bd + SWZ(brow * 128 + bq * 32 + j * 16)) = cvt4(pb[j]);
    }
    __syncthreads();

    const int NCH = NPTS / 32;      // 64
    int cur = 0;
    for (int i = 0; i < NCH; i++) {
        const bool more = (i + 1 < NCH);
        if (more) {
            const int kb = (i + 1) * 32;
#pragma unroll
            for (int j = 0; j < 4; j++) pa[j] = *(const float4*)(asrc + kb + 4 * j);
#pragma unroll
            for (int j = 0; j < 2; j++) pb[j] = *(const float4*)(bsrc + kb + 4 * j);
        }
        const char* Ab = sA[cur];
        const char* Bb = sB[cur];
#pragma unroll
        for (int kk = 0; kk < 32; kk += 8) {
            uint32_t a[2][4];
#pragma unroll
            for (int mb = 0; mb < 2; mb++) {
                int r0 = mg * 32 + mb * 16 + g;
                a[mb][0] = *(const uint32_t*)(Ab + SWZ(r0 * 128 + (kk + tig) * 4));
                a[mb][1] = *(const uint32_t*)(Ab + SWZ((r0 + 8) * 128 + (kk + tig) * 4));
                a[mb][2] = *(const uint32_t*)(Ab + SWZ(r0 * 128 + (kk + tig + 4) * 4));
                a[mb][3] = *(const uint32_t*)(Ab + SWZ((r0 + 8) * 128 + (kk + tig + 4) * 4));
            }
#pragma unroll
            for (int nb = 0; nb < 4; nb++) {
                int n = ng * 32 + nb * 8 + g;
                uint32_t b0 = *(const uint32_t*)(Bb + SWZ(n * 128 + (kk + tig) * 4));
                uint32_t b1 = *(const uint32_t*)(Bb + SWZ(n * 128 + (kk + tig + 4) * 4));
#pragma unroll
                for (int mb = 0; mb < 2; mb++) mma8(d[mb][nb], a[mb], b0, b1);
            }
        }
        if (more) {
            char* Ad = sA[cur ^ 1]; char* Bd = sB[cur ^ 1];
#pragma unroll
            for (int j = 0; j < 4; j++)
                *(uint4*)(Ad + SWZ(arow * 128 + ahalf * 64 + j * 16)) = cvt4(pa[j]);
#pragma unroll
            for (int j = 0; j < 2; j++)
                *(uint4*)(Bd + SWZ(brow * 128 + bq * 32 + j * 16)) = cvt4(pb[j]);
        }
        __syncthreads();
        cur ^= 1;
    }

    float* dst = reinterpret_cast<float*>(g_Xft) + reim;
#pragma unroll
    for (int mb = 0; mb < 2; mb++) {
#pragma unroll
        for (int nb = 0; nb < 4; nb++) {
            int f0 = ftile * 128 + mg * 32 + mb * 16 + g;
            int c0 = ng * 32 + nb * 8 + 2 * tig;
            dst[((size_t)(b * C_ + c0) * F1 + f0) * 2]           = d[mb][nb][0];
            dst[((size_t)(b * C_ + c0 + 1) * F1 + f0) * 2]       = d[mb][nb][1];
            dst[((size_t)(b * C_ + c0) * F1 + f0 + 8) * 2]       = d[mb][nb][2];
            dst[((size_t)(b * C_ + c0 + 1) * F1 + f0 + 8) * 2]   = d[mb][nb][3];
        }
    }
}

// ============================================================================
// Kernel 3: channel mixing + phi modulation + Hermitian expansion.
// Emits tf32-rounded planes g_xfre / g_xfmi  ({re} and {-im}).
// ============================================================================
__global__ __launch_bounds__(512) void k_mix(
    const float* __restrict__ w1re, const float* __restrict__ w1im,
    const float* __restrict__ w2re, const float* __restrict__ w2im)
{
    __shared__ float2 Xs[4][64][16];

    const int bid = blockIdx.x;
    const int xm  = bid >> 2;
    const int yh  = (bid >> 1) & 1;
    const int bh  = bid & 1;
    const int tid = threadIdx.x;

    {
        int row  = tid >> 1;
        int half = tid & 1;
        int br = row >> 6, ii = row & 63;
        const float2* src = g_Xft + ((size_t)((bh * 4 + br) * C_ + ii)) * F1
                            + xm * 32 + yh * 16 + half * 8;
#pragma unroll
        for (int j = 0; j < 4; j++) {
            float4 v = reinterpret_cast<const float4*>(src)[j];
            Xs[br][ii][half * 8 + j * 2]     = make_float2(v.x, v.y);
            Xs[br][ii][half * 8 + j * 2 + 1] = make_float2(v.z, v.w);
        }
    }
    __syncthreads();

    const int o   = tid >> 3;
    const int yq  = tid & 7;
    const int y   = yh * 16 + yq * 2;
    const int x32 = xm & 31;
    const float* wre = (xm < 32) ? w1re : w2re;
    const float* wim = (xm < 32) ? w1im : w2im;

    unsigned long long acc0[4] = {0ull, 0ull, 0ull, 0ull};
    unsigned long long acc1[4] = {0ull, 0ull, 0ull, 0ull};

#pragma unroll 4
    for (int ii = 0; ii < 64; ii++) {
        size_t wrow = (size_t)(ii * 64 + o) * 1024 + x32 * 32 + y;
        float2 wr = *reinterpret_cast<const float2*>(wre + wrow);
        float2 wi = *reinterpret_cast<const float2*>(wim + wrow);
        unsigned long long w0a = pack2(wr.x, wi.x);
        unsigned long long w0b = pack2(-wi.x, wr.x);
        unsigned long long w1a = pack2(wr.y, wi.y);
        unsigned long long w1b = pack2(-wi.y, wr.y);
#pragma unroll
        for (int br = 0; br < 4; br++) {
            float2 xv0 = Xs[br][ii][yq * 2];
            float2 xv1 = Xs[br][ii][yq * 2 + 1];
            fma2(acc0[br], pack2(xv0.x, xv0.x), w0a);
            fma2(acc0[br], pack2(xv0.y, xv0.y), w0b);
            fma2(acc1[br], pack2(xv1.x, xv1.x), w1a);
            fma2(acc1[br], pack2(xv1.y, xv1.y), w1b);
        }
    }

    const int sel = (xm < 32) ? 0 : 1;
#pragma unroll
    for (int br = 0; br < 4; br++) {
        int bb = bh * 4 + br;
#pragma unroll
        for (int pp = 0; pp < 2; pp++) {
            int yy = y + pp;
            float2 s = unpack2(pp ? acc1[br] : acc0[br]);
            float2 p = g_phi[sel * (B_ * 1024) + bb * 1024 + x32 * 32 + yy];
            float vr = f2tf_f(p.x * s.x - p.y * s.y);
            float vi = f2tf_f(p.x * s.y + p.y * s.x);
            int fm = xm * 32 + yy;
            size_t prim = (size_t)(bb * C_ + o) * MFRQ + fm;
            g_xfre[prim] = vr;
            g_xfmi[prim] = -vi;
            if (fm >= 64) {
                size_t mir = (size_t)(bb * C_ + (63 - o)) * MFRQ + (4095 - fm);
                g_xfre[mir] = vr;
                g_xfmi[mir] = vi;
            }
        }
    }
}

// ============================================================================
// Inverse NUFT via mma.sync tf32, cp.async fills, split-K over blockIdx.z.
// K-chunk layout: 32 cols = [16 re | 16 im] halves (any consistent K-order
// is valid as long as A and B agree):
//   A row n: [0:16) = pvre[n, kf..], [16:32) = pvim[n, kf..]
//   B row c: [0:16) = xfre[c, kf..], [16:32) = xfmi[c, kf..]
// grid (16 ntiles, 8 b, 2 kz), 256 threads, warp tile 32x32; atomicAdd merge.
// ============================================================================
__global__ __launch_bounds__(256, 2) void k_inverse(float* __restrict__ out)
{
    __shared__ __align__(128) char sA[2][16384];
    __shared__ __align__(128) char sB[2][8192];

    const int tid  = threadIdx.x;
    const int wid  = tid >> 5;
    const int lane = tid & 31;
    const int g    = lane >> 2;
    const int tig  = lane & 3;
    const int mg   = wid >> 1;      // 0..3
    const int ng   = wid & 1;       // 0..1
    const int ntile = blockIdx.x;
    const int b     = blockIdx.y;
    const int kz    = blockIdx.z;
    const int kbase = kz * (MFRQ / 2);   // 2016 (plane floats)

    // fill roles:
    // A: arow = tid>>1 (0..127), half = tid&1 selects re/im plane; 4 x 16B
    // B: brow = tid>>2 (0..63), bq = tid&3 selects 32B segment;     2 x 16B
    const int arow  = tid >> 1;
    const int ahalf = tid & 1;
    const float* asrc = (ahalf ? g_pvim : g_pvre)
                        + (size_t)(ntile * 128 + arow) * MFRQ + kbase;
    const int brow = tid >> 2;
    const int bq   = tid & 3;
    const float* bsrc = (bq < 2 ? g_xfre : g_xfmi)
                        + (size_t)(b * C_ + brow) * MFRQ + kbase + (bq & 1) * 8;

    const uint32_t sAu = smem_u32(&sA[0][0]);
    const uint32_t sBu = smem_u32(&sB[0][0]);
    const uint32_t aDst = sAu + 0;   // stage offset added per fill
    const int aRowOff = arow * 128 + ahalf * 64;
    const int bRowOff = brow * 128 + bq * 32;

    float d[2][4][4];
#pragma unroll
    for (int i = 0; i < 2; i++)
#pragma unroll
        for (int j = 0; j < 4; j++)
#pragma unroll
            for (int k = 0; k < 4; k++) d[i][j][k] = 0.f;

    const int NCH = (MFRQ / 2) / 16;   // 126 chunks (16 complex = 32 cols each)

    // ---- prologue: async-fill stages 0 and 1 ----
#pragma unroll
    for (int s = 0; s < 2; s++) {
        const int kf = s * 16;
        const uint32_t Ao = aDst + s * 16384;
        const uint32_t Bo = sBu + s * 8192;
#pragma unroll
        for (int q = 0; q < 4; q++)
            cpa16(Ao + SWZ(aRowOff + q * 16), asrc + kf + q * 4);
#pragma unroll
        for (int q = 0; q < 2; q++)
            cpa16(Bo + SWZ(bRowOff + q * 16), bsrc + kf + q * 4);
        CP_COMMIT();
    }

    for (int i = 0; i < NCH; i++) {
        const int cur = i & 1;
        if (i + 2 < NCH) CP_WAIT1(); else CP_WAIT0();
        __syncthreads();

        const char* Ab = sA[cur];
        const char* Bb = sB[cur];
#pragma unroll
        for (int kk = 0; kk < 32; kk += 8) {
            uint32_t a[2][4];
#pragma unroll
            for (int mb = 0; mb < 2; mb++) {
                int r0 = mg * 32 + mb * 16 + g;
                a[mb][0] = *(const uint32_t*)(Ab + SWZ(r0 * 128 + (kk + tig) * 4));
                a[mb][1] = *(const uint32_t*)(Ab + SWZ((r0 + 8) * 128 + (kk + tig) * 4));
                a[mb][2] = *(const uint32_t*)(Ab + SWZ(r0 * 128 + (kk + tig + 4) * 4));
                a[mb][3] = *(const uint32_t*)(Ab + SWZ((r0 + 8) * 128 + (kk + tig + 4) * 4));
            }
#pragma unroll
            for (int nb = 0; nb < 4; nb++) {
                int n = ng * 32 + nb * 8 + g;
                uint32_t b0 = *(const uint32_t*)(Bb + SWZ(n * 128 + (kk + tig) * 4));
                uint32_t b1 = *(const uint32_t*)(Bb + SWZ(n * 128 + (kk + tig + 4) * 4));
#pragma unroll
                for (int mb = 0; mb < 2; mb++) mma8(d[mb][nb], a[mb], b0, b1);
            }
        }
        __syncthreads();   // all warps done with stage `cur` before refill

        if (i + 2 < NCH) {
            const int kf = (i + 2) * 16;
            const uint32_t Ao = aDst + cur * 16384;
            const uint32_t Bo = sBu + cur * 8192;
#pragma unroll
            for (int q = 0; q < 4; q++)
                cpa16(Ao + SWZ(aRowOff + q * 16), asrc + kf + q * 4);
#pragma unroll
            for (int q = 0; q < 2; q++)
                cpa16(Bo + SWZ(bRowOff + q * 16), bsrc + kf + q * 4);
            CP_COMMIT();
        }
    }

    // epilogue: atomicAdd partials into zeroed out (2 addends/elem -> deterministic)
    const float sc = 2.0f / (float)NPTS;
#pragma unroll
    for (int mb = 0; mb < 2; mb++) {
#pragma unroll
        for (int nb = 0; nb < 4; nb++) {
            int n0 = ntile * 128 + mg * 32 + mb * 16 + g;
            int c0 = ng * 32 + nb * 8 + 2 * tig;
            atomicAdd(&out[(size_t)(b * C_ + c0) * NPTS + n0],         d[mb][nb][0] * sc);
            atomicAdd(&out[(size_t)(b * C_ + c0 + 1) * NPTS + n0],     d[mb][nb][1] * sc);
            atomicAdd(&out[(size_t)(b * C_ + c0) * NPTS + n0 + 8],     d[mb][nb][2] * sc);
            atomicAdd(&out[(size_t)(b * C_ + c0 + 1) * NPTS + n0 + 8], d[mb][nb][3] * sc);
        }
    }
}

// ============================================================================
extern "C" void kernel_launch(void* const* d_in, const int* in_sizes, int n_in,
                              void* d_out, int out_size)
{
    const float* x     = (const float*)d_in[0];
    const float* emb   = (const float*)d_in[1];
    const float* vf_re = (const float*)d_in[2];
    const float* vf_im = (const float*)d_in[3];
    const float* vi_re = (const float*)d_in[4];
    const float* vi_im = (const float*)d_in[5];
    const float* w1_re = (const float*)d_in[6];
    const float* w1_im = (const float*)d_in[7];
    const float* w2_re = (const float*)d_in[8];
    const float* w2_im = (const float*)d_in[9];
    const float* m1_re = (const float*)d_in[10];
    const float* m1_im = (const float*)d_in[11];
    const float* m2_re = (const float*)d_in[12];
    const float* m2_im = (const float*)d_in[13];
    float* out = (float*)d_out;

    k_zero<<<(B_ * C_ * NPTS) / 1024, 256>>>(out);
    k_preround<<<dim3((NPTS * MFRQ) / 1024, 2), 256>>>(vi_re, vi_im);
    k_phi<<<2048, 256>>>(emb, m1_re, m1_im, m2_re, m2_im);
    k_forward<<<dim3(16, 2, 8), 256>>>(x, vf_re, vf_im);
    k_mix<<<256, 512>>>(w1_re, w1_im, w2_re, w2_im);
    k_inverse<<<dim3(16, 8, 2), 256>>>(out);
}

// round 16
// speedup vs baseline: 1.2251x; 1.2251x over previous
#include <cuda_runtime.h>
#include <cstdint>

#define B_   8
#define C_   64
#define NPTS 2048
#define MFRQ 4032
#define F1   2048

// -------- scratch (device globals; no allocation in kernel_launch) ----------
__device__ __align__(16) float2 g_Xft[B_ * C_ * F1];   // forward result {re, im},  [b][c][f]
__device__ __align__(16) float2 g_xf [B_ * C_ * MFRQ]; // Hermitian-expanded {re, -im}, tf32-rounded
__device__ __align__(16) float  g_xtf[B_ * C_ * NPTS]; // x pre-rounded to tf32
__device__ float2 g_phi[2 * B_ * 1024];                // [mod][b][x(32)][y(32)]

// -------- packed f32x2 helpers (k_mix) --------------------------------------
__device__ __forceinline__ unsigned long long pack2(float lo, float hi) {
    unsigned long long r;
    asm("mov.b64 %0, {%1, %2};" : "=l"(r) : "f"(lo), "f"(hi));
    return r;
}
__device__ __forceinline__ float2 unpack2(unsigned long long v) {
    float2 r;
    asm("mov.b64 {%0, %1}, %2;" : "=f"(r.x), "=f"(r.y) : "l"(v));
    return r;
}
__device__ __forceinline__ void fma2(unsigned long long &d,
                                     unsigned long long a,
                                     unsigned long long b) {
    asm("fma.rn.f32x2 %0, %1, %2, %0;" : "+l"(d) : "l"(a), "l"(b));
}

// -------- tf32 mma.sync helpers (arch-portable PTX, compute_80+) ------------
#define SWZ(o) ((o) ^ (((o) >> 3) & 0x70))

__device__ __forceinline__ uint32_t f2tf(float f) {
    uint32_t r;
    asm("cvt.rna.tf32.f32 %0, %1;" : "=r"(r) : "f"(f));
    return r;
}
__device__ __forceinline__ float f2tf_f(float f) {
    return __uint_as_float(f2tf(f));
}
__device__ __forceinline__ uint4 cvt4(float4 v) {
    uint4 r;
    r.x = f2tf(v.x); r.y = f2tf(v.y); r.z = f2tf(v.z); r.w = f2tf(v.w);
    return r;
}
// D(16x8) += A(16x8) * B(8x8);  A row-major frag, B col-major frag, fp32 accum
__device__ __forceinline__ void mma8(float* d, const uint32_t* a,
                                     uint32_t b0, uint32_t b1) {
    asm volatile(
        "mma.sync.aligned.m16n8k8.row.col.f32.tf32.tf32.f32 "
        "{%0,%1,%2,%3}, {%4,%5,%6,%7}, {%8,%9}, {%0,%1,%2,%3};"
        : "+f"(d[0]), "+f"(d[1]), "+f"(d[2]), "+f"(d[3])
        : "r"(a[0]), "r"(a[1]), "r"(a[2]), "r"(a[3]), "r"(b0), "r"(b1));
}

// ============================================================================
// Kernel 0a: zero the output (split-K inverse accumulates atomically)
// ============================================================================
__global__ __launch_bounds__(256) void k_zero(float* __restrict__ out)
{
    const size_t i = ((size_t)blockIdx.x * 256 + threadIdx.x) * 4;
    *reinterpret_cast<float4*>(out + i) = make_float4(0.f, 0.f, 0.f, 0.f);
}

// ============================================================================
// Kernel 0b: pre-round x to tf32 (rna) — lets k_forward's B-fill skip cvt.
// 1,048,576 floats -> 1024 blocks x 256 thr x 4 floats.
// ============================================================================
__global__ __launch_bounds__(256) void k_xround(const float* __restrict__ x)
{
    const size_t i = ((size_t)blockIdx.x * 256 + threadIdx.x) * 4;
    float4 v = *reinterpret_cast<const float4*>(x + i);
    v.x = f2tf_f(v.x); v.y = f2tf_f(v.y); v.z = f2tf_f(v.z); v.w = f2tf_f(v.w);
    *reinterpret_cast<float4*>(g_xtf + i) = v;
}

// ============================================================================
// Kernel 1: phi[b,x,y] = sum_e mod[x,y,e] * emb[b,e]
// ============================================================================
__global__ __launch_bounds__(256) void k_phi(
    const float* __restrict__ emb,
    const float* __restrict__ m1re, const float* __restrict__ m1im,
    const float* __restrict__ m2re, const float* __restrict__ m2im)
{
    __shared__ float s_re[256];
    __shared__ float s_im[256];
    const int bid = blockIdx.x;
    const int mod = bid >> 10;
    const int xy  = bid & 1023;
    const int tid = threadIdx.x;

    const float* mre = (mod ? m2re : m1re) + (size_t)xy * 256;
    const float* mim = (mod ? m2im : m1im) + (size_t)xy * 256;
    s_re[tid] = mre[tid];
    s_im[tid] = mim[tid];
    __syncthreads();

    const int w = tid >> 5;
    const int l = tid & 31;
    float pr = 0.f, pi = 0.f;
#pragma unroll
    for (int j = 0; j < 8; j++) {
        int e = l + j * 32;
        float ee = emb[w * 256 + e];
        pr += s_re[e] * ee;
        pi += s_im[e] * ee;
    }
#pragma unroll
    for (int off = 16; off > 0; off >>= 1) {
        pr += __shfl_down_sync(0xffffffffu, pr, off);
        pi += __shfl_down_sync(0xffffffffu, pi, off);
    }
    if (l == 0) g_phi[mod * (B_ * 1024) + w * 1024 + xy] = make_float2(pr, pi);
}

// ============================================================================
// Forward NUFT via mma.sync tf32: D[f:128, c:64] = Vf_{re|im} @ xtf[b]^T.
// grid (16 ftiles, 2 reim, 8 b), 256 threads (8 warps), warp tile 32x32.
// B operand pre-rounded (g_xtf) -> B fill has no cvt.
// ============================================================================
__global__ __launch_bounds__(256, 2) void k_forward(
    const float* __restrict__ vfre,
    const float* __restrict__ vfim)
{
    __shared__ __align__(128) char sA[2][16384];
    __shared__ __align__(128) char sB[2][8192];

    const int tid  = threadIdx.x;
    const int wid  = tid >> 5;
    const int lane = tid & 31;
    const int g    = lane >> 2;
    const int tig  = lane & 3;
    const int mg   = wid >> 1;
    const int ng   = wid & 1;
    const int ftile = blockIdx.x;
    const int reim  = blockIdx.y;
    const int b     = blockIdx.z;
    const float* vf = reim ? vfim : vfre;
    const float* xb = g_xtf + (size_t)b * C_ * NPTS;

    const int arow  = tid >> 1;
    const int ahalf = tid & 1;
    const int fg    = ftile * 128 + arow;
    const int vrow  = (fg >> 5) * 63 + (fg & 31);
    const float* asrc = vf + (size_t)vrow * NPTS + ahalf * 16;
    const int brow = tid >> 2;
    const int bq   = tid & 3;
    const float* bsrc = xb + (size_t)brow * NPTS + bq * 8;

    float d[2][4][4];
#pragma unroll
    for (int i = 0; i < 2; i++)
#pragma unroll
        for (int j = 0; j < 4; j++)
#pragma unroll
            for (int k = 0; k < 4; k++) d[i][j][k] = 0.f;

    float4 pa[4], pb[2];
#pragma unroll
    for (int j = 0; j < 4; j++) pa[j] = *(const float4*)(asrc + 4 * j);
#pragma unroll
    for (int j = 0; j < 2; j++) pb[j] = *(const float4*)(bsrc + 4 * j);
    {
        char* Ad = sA[0]; char* Bd = sB[0];
#pragma unroll
        for (int j = 0; j < 4; j++)
            *(uint4*)(Ad + SWZ(arow * 128 + ahalf * 64 + j * 16)) = cvt4(pa[j]);
#pragma unroll
        for (int j = 0; j < 2; j++)
            *(uint4*)(Bd + SWZ(brow * 128 + bq * 32 + j * 16))
                = *reinterpret_cast<uint4*>(&pb[j]);
    }
    __syncthreads();

    const int NCH = NPTS / 32;      // 64
    int cur = 0;
    for (int i = 0; i < NCH; i++) {
        const bool more = (i + 1 < NCH);
        if (more) {
            const int kb = (i + 1) * 32;
#pragma unroll
            for (int j = 0; j < 4; j++) pa[j] = *(const float4*)(asrc + kb + 4 * j);
#pragma unroll
            for (int j = 0; j < 2; j++) pb[j] = *(const float4*)(bsrc + kb + 4 * j);
        }
        const char* Ab = sA[cur];
        const char* Bb = sB[cur];
#pragma unroll
        for (int kk = 0; kk < 32; kk += 8) {
            uint32_t a[2][4];
#pragma unroll
            for (int mb = 0; mb < 2; mb++) {
                int r0 = mg * 32 + mb * 16 + g;
                a[mb][0] = *(const uint32_t*)(Ab + SWZ(r0 * 128 + (kk + tig) * 4));
                a[mb][1] = *(const uint32_t*)(Ab + SWZ((r0 + 8) * 128 + (kk + tig) * 4));
                a[mb][2] = *(const uint32_t*)(Ab + SWZ(r0 * 128 + (kk + tig + 4) * 4));
                a[mb][3] = *(const uint32_t*)(Ab + SWZ((r0 + 8) * 128 + (kk + tig + 4) * 4));
            }
#pragma unroll
            for (int nb = 0; nb < 4; nb++) {
                int n = ng * 32 + nb * 8 + g;
                uint32_t b0 = *(const uint32_t*)(Bb + SWZ(n * 128 + (kk + tig) * 4));
                uint32_t b1 = *(const uint32_t*)(Bb + SWZ(n * 128 + (kk + tig + 4) * 4));
#pragma unroll
                for (int mb = 0; mb < 2; mb++) mma8(d[mb][nb], a[mb], b0, b1);
            }
        }
        if (more) {
            char* Ad = sA[cur ^ 1]; char* Bd = sB[cur ^ 1];
#pragma unroll
            for (int j = 0; j < 4; j++)
                *(uint4*)(Ad + SWZ(arow * 128 + ahalf * 64 + j * 16)) = cvt4(pa[j]);
#pragma unroll
            for (int j = 0; j < 2; j++)
                *(uint4*)(Bd + SWZ(brow * 128 + bq * 32 + j * 16))
                    = *reinterpret_cast<uint4*>(&pb[j]);
        }
        __syncthreads();
        cur ^= 1;
    }

    // epilogue: scatter D into g_Xft interleaved slot `reim`
    float* dst = reinterpret_cast<float*>(g_Xft) + reim;
#pragma unroll
    for (int mb = 0; mb < 2; mb++) {
#pragma unroll
        for (int nb = 0; nb < 4; nb++) {
            int f0 = ftile * 128 + mg * 32 + mb * 16 + g;
            int c0 = ng * 32 + nb * 8 + 2 * tig;
            dst[((size_t)(b * C_ + c0) * F1 + f0) * 2]           = d[mb][nb][0];
            dst[((size_t)(b * C_ + c0 + 1) * F1 + f0) * 2]       = d[mb][nb][1];
            dst[((size_t)(b * C_ + c0) * F1 + f0 + 8) * 2]       = d[mb][nb][2];
            dst[((size_t)(b * C_ + c0 + 1) * F1 + f0 + 8) * 2]   = d[mb][nb][3];
        }
    }
}

// ============================================================================
// Kernel 3: channel mixing + phi modulation + Hermitian expansion.
// g_xf stored [b][c][f] float2 {re, -im}, tf32-rounded at the source so the
// inverse's B-fill needs no cvt.
// ============================================================================
__global__ __launch_bounds__(512) void k_mix(
    const float* __restrict__ w1re, const float* __restrict__ w1im,
    const float* __restrict__ w2re, const float* __restrict__ w2im)
{
    __shared__ float2 Xs[4][64][16];

    const int bid = blockIdx.x;
    const int xm  = bid >> 2;
    const int yh  = (bid >> 1) & 1;
    const int bh  = bid & 1;
    const int tid = threadIdx.x;

    {
        int row  = tid >> 1;
        int half = tid & 1;
        int br = row >> 6, ii = row & 63;
        const float2* src = g_Xft + ((size_t)((bh * 4 + br) * C_ + ii)) * F1
                            + xm * 32 + yh * 16 + half * 8;
#pragma unroll
        for (int j = 0; j < 4; j++) {
            float4 v = reinterpret_cast<const float4*>(src)[j];
            Xs[br][ii][half * 8 + j * 2]     = make_float2(v.x, v.y);
            Xs[br][ii][half * 8 + j * 2 + 1] = make_float2(v.z, v.w);
        }
    }
    __syncthreads();

    const int o   = tid >> 3;
    const int yq  = tid & 7;
    const int y   = yh * 16 + yq * 2;
    const int x32 = xm & 31;
    const float* wre = (xm < 32) ? w1re : w2re;
    const float* wim = (xm < 32) ? w1im : w2im;

    unsigned long long acc0[4] = {0ull, 0ull, 0ull, 0ull};
    unsigned long long acc1[4] = {0ull, 0ull, 0ull, 0ull};

#pragma unroll 4
    for (int ii = 0; ii < 64; ii++) {
        size_t wrow = (size_t)(ii * 64 + o) * 1024 + x32 * 32 + y;
        float2 wr = *reinterpret_cast<const float2*>(wre + wrow);
        float2 wi = *reinterpret_cast<const float2*>(wim + wrow);
        unsigned long long w0a = pack2(wr.x, wi.x);
        unsigned long long w0b = pack2(-wi.x, wr.x);
        unsigned long long w1a = pack2(wr.y, wi.y);
        unsigned long long w1b = pack2(-wi.y, wr.y);
#pragma unroll
        for (int br = 0; br < 4; br++) {
            float2 xv0 = Xs[br][ii][yq * 2];
            float2 xv1 = Xs[br][ii][yq * 2 + 1];
            fma2(acc0[br], pack2(xv0.x, xv0.x), w0a);
            fma2(acc0[br], pack2(xv0.y, xv0.y), w0b);
            fma2(acc1[br], pack2(xv1.x, xv1.x), w1a);
            fma2(acc1[br], pack2(xv1.y, xv1.y), w1b);
        }
    }

    const int sel = (xm < 32) ? 0 : 1;
#pragma unroll
    for (int br = 0; br < 4; br++) {
        int bb = bh * 4 + br;
#pragma unroll
        for (int pp = 0; pp < 2; pp++) {
            int yy = y + pp;
            float2 s = unpack2(pp ? acc1[br] : acc0[br]);
            float2 p = g_phi[sel * (B_ * 1024) + bb * 1024 + x32 * 32 + yy];
            float vr = f2tf_f(p.x * s.x - p.y * s.y);
            float vi = f2tf_f(p.x * s.y + p.y * s.x);
            int fm = xm * 32 + yy;
            g_xf[((size_t)(bb * C_ + o)) * MFRQ + fm] = make_float2(vr, -vi);
            if (fm >= 64)
                g_xf[((size_t)(bb * C_ + (63 - o))) * MFRQ + (4095 - fm)] = make_float2(vr, vi);
        }
    }
}

// ============================================================================
// Inverse NUFT via mma.sync tf32, split-K over blockIdx.z (2 halves of K=8064):
// D[n:128, c:64] += A[n][.] * B[c][.]  (atomicAdd into zeroed out)
//   A[n][2j,2j+1] = {Vi_re[n,j], Vi_im[n,j]};  B[c][2j,2j+1] = {xf_re, -xf_im}.
// grid (16 ntiles, 8 b, 2 kz), 256 threads (8 warps), warp tile 32x32.
// B operand pre-rounded by k_mix -> B fill has no cvt.
// ============================================================================
__global__ __launch_bounds__(256, 2) void k_inverse(
    const float* __restrict__ vire,
    const float* __restrict__ viim,
    float* __restrict__ out)
{
    __shared__ __align__(128) char sA[2][16384];
    __shared__ __align__(128) char sB[2][8192];

    const int tid  = threadIdx.x;
    const int wid  = tid >> 5;
    const int lane = tid & 31;
    const int g    = lane >> 2;
    const int tig  = lane & 3;
    const int mg   = wid >> 1;      // 0..3
    const int ng   = wid & 1;       // 0..1
    const int ntile = blockIdx.x;
    const int b     = blockIdx.y;
    const int kz    = blockIdx.z;   // 0..1 split-K half
    const int kbase = kz * (MFRQ / 2);   // 2016 complex

    const int arow  = tid >> 1;
    const int ahalf = tid & 1;
    const float* vre = vire + (size_t)(ntile * 128 + arow) * MFRQ + kbase + ahalf * 8;
    const float* vim = viim + (size_t)(ntile * 128 + arow) * MFRQ + kbase + ahalf * 8;
    const int brow = tid >> 2;
    const int bq   = tid & 3;
    const float2* bsrc = g_xf + (size_t)(b * C_ + brow) * MFRQ + kbase + bq * 4;

    float d[2][4][4];
#pragma unroll
    for (int i = 0; i < 2; i++)
#pragma unroll
        for (int j = 0; j < 4; j++)
#pragma unroll
            for (int k = 0; k < 4; k++) d[i][j][k] = 0.f;

    float4 par[2], pai[2], pb[2];
#pragma unroll
    for (int j = 0; j < 2; j++) {
        par[j] = *(const float4*)(vre + 4 * j);
        pai[j] = *(const float4*)(vim + 4 * j);
        pb[j]  = *(const float4*)(bsrc + 2 * j);
    }
    {
        char* Ad = sA[0]; char* Bd = sB[0];
        const int db = arow * 128 + ahalf * 64;
#pragma unroll
        for (int j = 0; j < 2; j++) {
            uint4 lo = make_uint4(f2tf(par[j].x), f2tf(pai[j].x), f2tf(par[j].y), f2tf(pai[j].y));
            uint4 hi = make_uint4(f2tf(par[j].z), f2tf(pai[j].z), f2tf(par[j].w), f2tf(pai[j].w));
            *(uint4*)(Ad + SWZ(db + j * 32))      = lo;
            *(uint4*)(Ad + SWZ(db + j * 32 + 16)) = hi;
            *(uint4*)(Bd + SWZ(brow * 128 + bq * 32 + j * 16))
                = *reinterpret_cast<uint4*>(&pb[j]);
        }
    }
    __syncthreads();

    const int NCH = (MFRQ / 2) / 16;   // 126 chunks per split-K half
    int cur = 0;
    for (int i = 0; i < NCH; i++) {
        const bool more = (i + 1 < NCH);
        if (more) {
            const int kf = (i + 1) * 16;
#pragma unroll
            for (int j = 0; j < 2; j++) {
                par[j] = *(const float4*)(vre + kf + 4 * j);
                pai[j] = *(const float4*)(vim + kf + 4 * j);
                pb[j]  = *(const float4*)(bsrc + kf + 2 * j);
            }
        }
        const char* Ab = sA[cur];
        const char* Bb = sB[cur];
#pragma unroll
        for (int kk = 0; kk < 32; kk += 8) {
            uint32_t a[2][4];
#pragma unroll
            for (int mb = 0; mb < 2; mb++) {
                int r0 = mg * 32 + mb * 16 + g;
                a[mb][0] = *(const uint32_t*)(Ab + SWZ(r0 * 128 + (kk + tig) * 4));
                a[mb][1] = *(const uint32_t*)(Ab + SWZ((r0 + 8) * 128 + (kk + tig) * 4));
                a[mb][2] = *(const uint32_t*)(Ab + SWZ(r0 * 128 + (kk + tig + 4) * 4));
                a[mb][3] = *(const uint32_t*)(Ab + SWZ((r0 + 8) * 128 + (kk + tig + 4) * 4));
            }
#pragma unroll
            for (int nb = 0; nb < 4; nb++) {
                int n = ng * 32 + nb * 8 + g;
                uint32_t b0 = *(const uint32_t*)(Bb + SWZ(n * 128 + (kk + tig) * 4));
                uint32_t b1 = *(const uint32_t*)(Bb + SWZ(n * 128 + (kk + tig + 4) * 4));
#pragma unroll
                for (int mb = 0; mb < 2; mb++) mma8(d[mb][nb], a[mb], b0, b1);
            }
        }
        if (more) {
            char* Ad = sA[cur ^ 1]; char* Bd = sB[cur ^ 1];
            const int db = arow * 128 + ahalf * 64;
#pragma unroll
            for (int j = 0; j < 2; j++) {
                uint4 lo = make_uint4(f2tf(par[j].x), f2tf(pai[j].x), f2tf(par[j].y), f2tf(pai[j].y));
                uint4 hi = make_uint4(f2tf(par[j].z), f2tf(pai[j].z), f2tf(par[j].w), f2tf(pai[j].w));
                *(uint4*)(Ad + SWZ(db + j * 32))      = lo;
                *(uint4*)(Ad + SWZ(db + j * 32 + 16)) = hi;
                *(uint4*)(Bd + SWZ(brow * 128 + bq * 32 + j * 16))
                    = *reinterpret_cast<uint4*>(&pb[j]);
            }
        }
        __syncthreads();
        cur ^= 1;
    }

    // epilogue: atomicAdd partials into zeroed out (2 addends/elem -> deterministic)
    const float sc = 2.0f / (float)NPTS;
#pragma unroll
    for (int mb = 0; mb < 2; mb++) {
#pragma unroll
        for (int nb = 0; nb < 4; nb++) {
            int n0 = ntile * 128 + mg * 32 + mb * 16 + g;
            int c0 = ng * 32 + nb * 8 + 2 * tig;
            atomicAdd(&out[(size_t)(b * C_ + c0) * NPTS + n0],         d[mb][nb][0] * sc);
            atomicAdd(&out[(size_t)(b * C_ + c0 + 1) * NPTS + n0],     d[mb][nb][1] * sc);
            atomicAdd(&out[(size_t)(b * C_ + c0) * NPTS + n0 + 8],     d[mb][nb][2] * sc);
            atomicAdd(&out[(size_t)(b * C_ + c0 + 1) * NPTS + n0 + 8], d[mb][nb][3] * sc);
        }
    }
}

// ============================================================================
extern "C" void kernel_launch(void* const* d_in, const int* in_sizes, int n_in,
                              void* d_out, int out_size)
{
    const float* x     = (const float*)d_in[0];
    const float* emb   = (const float*)d_in[1];
    const float* vf_re = (const float*)d_in[2];
    const float* vf_im = (const float*)d_in[3];
    const float* vi_re = (const float*)d_in[4];
    const float* vi_im = (const float*)d_in[5];
    const float* w1_re = (const float*)d_in[6];
    const float* w1_im = (const float*)d_in[7];
    const float* w2_re = (const float*)d_in[8];
    const float* w2_im = (const float*)d_in[9];
    const float* m1_re = (const float*)d_in[10];
    const float* m1_im = (const float*)d_in[11];
    const float* m2_re = (const float*)d_in[12];
    const float* m2_im = (const float*)d_in[13];
    float* out = (float*)d_out;

    k_zero<<<(B_ * C_ * NPTS) / 1024, 256>>>(out);
    k_xround<<<(B_ * C_ * NPTS) / 1024, 256>>>(x);
    k_phi<<<2048, 256>>>(emb, m1_re, m1_im, m2_re, m2_im);
    k_forward<<<dim3(16, 2, 8), 256>>>(vf_re, vf_im);
    k_mix<<<256, 512>>>(w1_re, w1_im, w2_re, w2_im);
    k_inverse<<<dim3(16, 8, 2), 256>>>(vi_re, vi_im, out);
}